// round 4
// baseline (speedup 1.0000x reference)
#include <cuda_runtime.h>
#include <cuda_bf16.h>
#include <math.h>

// Inputs (metadata order): Xemb [8192,128] f32, scores f32 (unused),
// h_bias scalar f32, labels i32 (unused), pos_idx [P,2] i32, neg_idx [P,2] i32.
// Output: 2 floats {pos_loss, neg_loss}.

#define NUM_BLOCKS 888    // 148 SMs * 6 (one wave at occ=6)
#define THREADS    256    // 8 warps/block

__device__ float2 g_partials[NUM_BLOCKS];
__device__ unsigned int g_done_count = 0;

// 16 lanes per pair: each lane loads 2 float4 from each row (4 float4 live).
__device__ __forceinline__ float pair_partial16(const float* __restrict__ X,
                                                int2 idx, int sub)
{
    const float4* ra = (const float4*)(X + (size_t)idx.x * 128);
    const float4* rb = (const float4*)(X + (size_t)idx.y * 128);
    float4 a0 = __ldg(ra + sub);
    float4 a1 = __ldg(ra + sub + 16);
    float4 b0 = __ldg(rb + sub);
    float4 b1 = __ldg(rb + sub + 16);

    float s = 0.f, d;
    d = a0.x - b0.x; s += d * d;  d = a0.y - b0.y; s += d * d;
    d = a0.z - b0.z; s += d * d;  d = a0.w - b0.w; s += d * d;
    d = a1.x - b1.x; s += d * d;  d = a1.y - b1.y; s += d * d;
    d = a1.z - b1.z; s += d * d;  d = a1.w - b1.w; s += d * d;
    return s;
}

__global__ __launch_bounds__(THREADS, 6)
void pair_loss_fused_kernel(const float* __restrict__ X,
                            const float* __restrict__ h_bias,
                            const int2* __restrict__ pos_idx,
                            const int2* __restrict__ neg_idx,
                            int P,
                            float* __restrict__ out)
{
    const int lane  = threadIdx.x & 31;
    const int warp  = threadIdx.x >> 5;
    const int grp   = lane >> 4;       // 0..1: which pair within the warp
    const int sub   = lane & 15;       // 0..15: lane within the pair group
    const int gwarp = (blockIdx.x * blockDim.x + threadIdx.x) >> 5;
    const int G     = ((NUM_BLOCKS * THREADS) >> 5) * 2;   // total groups
    const long g0   = (long)gwarp * 2;                     // warp's first group id
    const long ggrp = g0 + grp;                            // this group's id

    const float bias = log1pf(expf(*h_bias));  // softplus

    float pos_acc = 0.0f;   // per-lane partial (no per-pair reduce needed)
    float neg_acc = 0.0f;

    // ---- positive pairs (no per-pair reduce: per-lane partials) ----
    {
        const long nIter = (P > g0) ? ((P - 1 - g0) / G + 1) : 0;
        long t = ggrp;
        #pragma unroll 2
        for (long k = 0; k < nIter; k++, t += G) {
            const bool valid = (t < P);
            const int2 idx = valid ? __ldg(&pos_idx[t]) : make_int2(0, 0);
            // invalid -> rows identical -> contributes exactly 0
            pos_acc += pair_partial16(X, idx, sub);
        }
    }

    // ---- negative pairs ----
    {
        const long nIter = (P > g0) ? ((P - 1 - g0) / G + 1) : 0;
        long t = ggrp;
        #pragma unroll 2
        for (long k = 0; k < nIter; k++, t += G) {
            const bool valid = (t < P);
            const int2 idx = valid ? __ldg(&neg_idx[t]) : make_int2(0, 0);
            float s = pair_partial16(X, idx, sub);
            // reduce within the 16-lane group (xor offsets < 16 stay in-group)
            s += __shfl_xor_sync(0xFFFFFFFFu, s, 1);
            s += __shfl_xor_sync(0xFFFFFFFFu, s, 2);
            s += __shfl_xor_sync(0xFFFFFFFFu, s, 4);
            s += __shfl_xor_sync(0xFFFFFFFFu, s, 8);
            const float dd = sqrtf(s);
            const float r  = fmaxf(bias - dd, 0.0f);
            neg_acc += (valid && sub == 0) ? r * r : 0.0f;
        }
    }

    // ---- block reduce ----
    __shared__ float s_pos[THREADS / 32];
    __shared__ float s_neg[THREADS / 32];
    float p = pos_acc, n = neg_acc;
    #pragma unroll
    for (int o = 16; o > 0; o >>= 1) {
        p += __shfl_xor_sync(0xFFFFFFFFu, p, o);
        n += __shfl_xor_sync(0xFFFFFFFFu, n, o);
    }
    if (lane == 0) { s_pos[warp] = p; s_neg[warp] = n; }
    __syncthreads();

    __shared__ bool s_is_last;
    if (warp == 0) {
        float pp = (lane < THREADS / 32) ? s_pos[lane] : 0.0f;
        float nn = (lane < THREADS / 32) ? s_neg[lane] : 0.0f;
        #pragma unroll
        for (int o = 4; o > 0; o >>= 1) {
            pp += __shfl_xor_sync(0xFFFFFFFFu, pp, o);
            nn += __shfl_xor_sync(0xFFFFFFFFu, nn, o);
        }
        if (lane == 0) {
            g_partials[blockIdx.x] = make_float2(pp, nn);
            __threadfence();
            unsigned int prev = atomicAdd(&g_done_count, 1u);
            s_is_last = (prev == (unsigned int)(gridDim.x - 1));
        }
    }
    __syncthreads();

    // ---- last block: final deterministic reduction in double ----
    if (s_is_last) {
        double ps = 0.0, ns = 0.0;
        for (int i = threadIdx.x; i < NUM_BLOCKS; i += THREADS) {
            float2 v = g_partials[i];
            ps += (double)v.x;
            ns += (double)v.y;
        }
        #pragma unroll
        for (int o = 16; o > 0; o >>= 1) {
            ps += __shfl_xor_sync(0xFFFFFFFFu, ps, o);
            ns += __shfl_xor_sync(0xFFFFFFFFu, ns, o);
        }
        __shared__ double sp[THREADS / 32], sn[THREADS / 32];
        if (lane == 0) { sp[warp] = ps; sn[warp] = ns; }
        __syncthreads();
        if (threadIdx.x == 0) {
            double tp = 0.0, tn = 0.0;
            for (int w = 0; w < THREADS / 32; w++) { tp += sp[w]; tn += sn[w]; }
            out[0] = (float)(0.5 * tp / (double)P);
            out[1] = (float)(0.5 * tn / (double)P);
            g_done_count = 0;   // reset for next graph replay
        }
    }
}

extern "C" void kernel_launch(void* const* d_in, const int* in_sizes, int n_in,
                              void* d_out, int out_size)
{
    const float* X      = (const float*)d_in[0];
    const float* h_bias = (const float*)d_in[2];
    const int2*  pos    = (const int2*)d_in[4];
    const int2*  neg    = (const int2*)d_in[5];
    const int P = in_sizes[4] / 2;

    pair_loss_fused_kernel<<<NUM_BLOCKS, THREADS>>>(X, h_bias, pos, neg, P, (float*)d_out);
}